// round 5
// baseline (speedup 1.0000x reference)
#include <cuda_runtime.h>
#include <math.h>

#define NB   128          // persistent blocks (all resident on 148 SMs)
#define NT   256
#define B_   64
#define T_   512
#define V_   256
#define MEM_ 1024
#define KT   64

// ---------------- scratch (__device__ globals: allocation is forbidden) -------
__device__ float g_h0[B_ * MEM_];
__device__ float g_c0[B_ * MEM_];
__device__ float g_c1[B_ * MEM_];
__device__ float g_h1seq[(T_ + 1) * B_ * MEM_];           // slot t+1 = h1 at step t
__device__ __align__(16) float g_part0[4 * B_ * MEM_ * 4]; // [ks][row][mc][gate i,j,f,o]
__device__ __align__(16) float g_part1[4 * B_ * MEM_ * 4];
__device__ unsigned int g_bar_count = 0;
__device__ unsigned int g_bar_gen   = 0;

// packed fp32x2 FMA (B300: FFMA2 only reachable via PTX fma.rn.f32x2)
#define FFMA2(acc, a, b) asm("fma.rn.f32x2 %0, %1, %2, %0;" : "+l"(acc) : "l"(a), "l"(b))
#define PACK2(d, lo, hi) asm("mov.b64 %0, {%1, %2};" : "=l"(d) : "f"(lo), "f"(hi))

// ---------------- software grid barrier (all NB blocks resident) --------------
__device__ __forceinline__ void grid_barrier() {
    __threadfence();                 // push my stores to L2; IVALL invalidates stale L1
    __syncthreads();
    if (threadIdx.x == 0) {
        unsigned int my = *(volatile unsigned int*)&g_bar_gen;
        if (atomicAdd(&g_bar_count, 1) == NB - 1) {
            atomicExch(&g_bar_count, 0);
            __threadfence();
            atomicExch(&g_bar_gen, my + 1);
        } else {
            while (*(volatile unsigned int*)&g_bar_gen == my) { __nanosleep(64); }
        }
        __threadfence();             // reader-side: invalidate this SM's L1 after release
    }
    __syncthreads();
}

// ---------------- GEMM phase: partial z for one layer, one timestep -----------
// blocks: tile = blk&31 (32 memcols each), ks = blk>>5 (K split by 4)
// thread: 4 rows x 2 memcols x 4 gates -> 16 f32x2 accumulators
__device__ __forceinline__ void gemm_phase(
    const float* __restrict__ A0, long long strideA0, int K0,   // first operand rows
    const float* __restrict__ A1,                               // h (stride MEM_)
    const float* __restrict__ W,                                // [K][4096]
    int Kq,                                                     // K/4 slice length
    float* __restrict__ part)
{
    __shared__ float a_sm[64][KT];                              // [row][kk]
    __shared__ __align__(16) unsigned long long w_sm[KT][2][32];// [kk][gatepair][mc]

    const int tid  = threadIdx.x;
    const int rg   = tid >> 4;            // 0..15 -> rows 4rg..4rg+3
    const int mg   = tid & 15;            // -> memcols mc0+2mg, +1
    const int tile = blockIdx.x & 31;
    const int ks   = blockIdx.x >> 5;
    const int mc0  = tile * 32;
    const int kbase = ks * Kq;
    const int nchunks = Kq / KT;

    float ra[16];                         // prefetch staging (regs)
    float rw[32];

    auto load_chunk = [&](int c) {
        int kg = kbase + c * KT;          // KT divides all A0/A1 boundaries
        const float* Ab; long long st; int kl;
        if (kg < K0) { Ab = A0; st = strideA0; kl = kg; }
        else         { Ab = A1; st = MEM_;     kl = kg - K0; }
        #pragma unroll
        for (int i = 0; i < 16; ++i) {    // A: 64 rows x 64 kk, kk fastest (coalesced)
            int idx = tid + i * NT;
            int kk = idx & 63, row = idx >> 6;
            ra[i] = Ab[(long long)row * st + kl + kk];
        }
        #pragma unroll
        for (int i = 0; i < 8; ++i) {     // W: 64 kk x 32 mc x 4 gates
            int idx = tid + i * NT;
            int mc = idx & 31, kk = idx >> 5;
            const float* wp = W + (long long)(kg + kk) * 4096 + mc0 + mc;
            rw[i * 4 + 0] = wp[0];
            rw[i * 4 + 1] = wp[1024];
            rw[i * 4 + 2] = wp[2048];
            rw[i * 4 + 3] = wp[3072];
        }
    };
    auto store_chunk = [&]() {
        #pragma unroll
        for (int i = 0; i < 16; ++i) {
            int idx = tid + i * NT;
            int kk = idx & 63, row = idx >> 6;
            a_sm[row][kk] = ra[i];        // lanes: kk contiguous -> conflict-free
        }
        #pragma unroll
        for (int i = 0; i < 8; ++i) {
            int idx = tid + i * NT;
            int mc = idx & 31, kk = idx >> 5;
            unsigned long long p0, p1;
            PACK2(p0, rw[i * 4 + 0], rw[i * 4 + 1]);   // {wi, wj}
            PACK2(p1, rw[i * 4 + 2], rw[i * 4 + 3]);   // {wf, wo}
            w_sm[kk][0][mc] = p0;
            w_sm[kk][1][mc] = p1;
        }
    };

    unsigned long long acc[2][4][2];      // [m][row][gatepair]
    #pragma unroll
    for (int m = 0; m < 2; ++m)
        #pragma unroll
        for (int r = 0; r < 4; ++r) { acc[m][r][0] = 0ull; acc[m][r][1] = 0ull; }

    load_chunk(0);
    for (int c = 0; c < nchunks; ++c) {
        __syncthreads();
        store_chunk();
        __syncthreads();
        if (c + 1 < nchunks) load_chunk(c + 1);   // global loads hidden under compute

        #pragma unroll 8
        for (int kk = 0; kk < KT; ++kk) {
            unsigned long long ad[4];
            #pragma unroll
            for (int r = 0; r < 4; ++r) {
                float a = a_sm[4 * rg + r][kk];   // 16-lane broadcast
                PACK2(ad[r], a, a);
            }
            ulonglong2 wp0 = *reinterpret_cast<const ulonglong2*>(&w_sm[kk][0][2 * mg]);
            ulonglong2 wp1 = *reinterpret_cast<const ulonglong2*>(&w_sm[kk][1][2 * mg]);
            #pragma unroll
            for (int r = 0; r < 4; ++r) {
                FFMA2(acc[0][r][0], ad[r], wp0.x);
                FFMA2(acc[0][r][1], ad[r], wp1.x);
                FFMA2(acc[1][r][0], ad[r], wp0.y);
                FFMA2(acc[1][r][1], ad[r], wp1.y);
            }
        }
    }

    // write partials: part[ks][row][mc][{zi,zj,zf,zo}]
    #pragma unroll
    for (int m = 0; m < 2; ++m)
        #pragma unroll
        for (int r = 0; r < 4; ++r) {
            int row = 4 * rg + r;
            int mc  = mc0 + 2 * mg + m;
            long long base = (((long long)ks * 64 + row) * 1024 + mc) * 4;
            *reinterpret_cast<unsigned long long*>(&part[base])     = acc[m][r][0];
            *reinterpret_cast<unsigned long long*>(&part[base + 2]) = acc[m][r][1];
        }
}

// ---------------- gate phase: reduce 4 partials, nonlinearity, c/h update -----
__device__ __forceinline__ void gate_phase(
    const float* __restrict__ part, const float* __restrict__ bias,
    float* __restrict__ cst, float* __restrict__ hout)
{
    int base = blockIdx.x * 512 + threadIdx.x;
    #pragma unroll
    for (int j = 0; j < 2; ++j) {
        int idx = base + j * 256;             // 0..65535 = 64 rows x 1024 memcols
        int row = idx >> 10, mc = idx & 1023;
        float zi = 0.f, zj = 0.f, zf = 0.f, zo = 0.f;
        #pragma unroll
        for (int ks = 0; ks < 4; ++ks) {
            float4 p = *reinterpret_cast<const float4*>(
                &part[(((long long)ks * 64 + row) * 1024 + mc) * 4]);
            zi += p.x; zj += p.y; zf += p.z; zo += p.w;
        }
        zi += bias[mc];
        zj += bias[1024 + mc];
        zf += bias[2048 + mc] + 1.0f;          // FORGET_BIAS
        zo += bias[3072 + mc];
        float ig = 1.f / (1.f + expf(-zi));
        float fg = 1.f / (1.f + expf(-zf));
        float og = 1.f / (1.f + expf(-zo));
        float jt = tanhf(zj);
        int o = row * 1024 + mc;
        float c = cst[o] * fg + ig * jt;
        cst[o]  = c;
        hout[o] = tanhf(c) * og;
    }
}

// ---------------- persistent kernel: init + 512 steps + final_state -----------
__global__ void __launch_bounds__(NT, 1) lstm_persistent(
    const float* __restrict__ x,
    const float* __restrict__ s0, const float* __restrict__ s1,
    const float* __restrict__ W0, const float* __restrict__ b0,
    const float* __restrict__ W1, const float* __restrict__ b1,
    float* __restrict__ fs_out)
{
    {   // unpack states: c|h each 64x1024
        int base = blockIdx.x * 512 + threadIdx.x;
        #pragma unroll
        for (int j = 0; j < 2; ++j) {
            int idx = base + j * 256;
            int b = idx >> 10, m = idx & 1023;
            g_c0[idx]    = s0[b * 2048 + m];
            g_h0[idx]    = s0[b * 2048 + 1024 + m];
            g_c1[idx]    = s1[b * 2048 + m];
            g_h1seq[idx] = s1[b * 2048 + 1024 + m];   // slot 0 = initial h1
        }
    }
    grid_barrier();

    for (int t = 0; t < T_; ++t) {
        // layer 0: A = [x_t (K0=256) ; h0 (1024)], K=1280, slice 320
        gemm_phase(x + (long long)t * V_, (long long)T_ * V_, V_, g_h0, W0, 320, g_part0);
        grid_barrier();
        gate_phase(g_part0, b0, g_c0, g_h0);
        grid_barrier();
        // layer 1: A = [h0_t (1024) ; h1_{t-1} (1024)], K=2048, slice 512
        gemm_phase(g_h0, MEM_, MEM_, g_h1seq + (long long)t * B_ * MEM_, W1, 512, g_part1);
        grid_barrier();
        gate_phase(g_part1, b1, g_c1, g_h1seq + (long long)(t + 1) * B_ * MEM_);
        // no barrier needed: next gemm_phase touches only part0/h0/x (disjoint)
    }
    grid_barrier();

    {   // final_state = stack([concat(c0,h0), concat(c1,h1)])  -> 2*64*2048 floats
        int base = blockIdx.x * 2048 + threadIdx.x;
        #pragma unroll
        for (int j = 0; j < 8; ++j) {
            int idx = base + j * 256;
            int l = idx >> 17, rem = idx & 131071;
            int b = rem >> 11, q = rem & 2047;
            int m = q & 1023, ish = q >> 10;
            float v;
            if (l == 0) v = ish ? g_h0[b * 1024 + m] : g_c0[b * 1024 + m];
            else        v = ish ? g_h1seq[(long long)T_ * B_ * MEM_ + b * 1024 + m]
                                : g_c1[b * 1024 + m];
            fs_out[idx] = v;
        }
    }
}

// ---------------- output projection: out = h1_seq @ W_out + b_out -------------
__global__ void __launch_bounds__(256) proj_kernel(const float* __restrict__ Wout,
                                                   const float* __restrict__ bout,
                                                   float* __restrict__ out) {
    __shared__ float As[32][33];
    __shared__ __align__(16) float Ws[32][32];
    const int tid = threadIdx.x;
    const int rtile = blockIdx.x;        // 0..1023
    const int ctile = blockIdx.y;        // 0..7
    const int r  = tid >> 3;
    const int c4 = tid & 7;
    float acc[4] = {0.f, 0.f, 0.f, 0.f};

    for (int k0 = 0; k0 < MEM_; k0 += 32) {
        #pragma unroll
        for (int i = 0; i < 4; ++i) {
            int idx = tid + i * 256;
            int rr = idx >> 5, kk = idx & 31;
            int rglob = rtile * 32 + rr;             // row = b*512 + t
            int b = rglob >> 9, tt = rglob & 511;
            As[rr][kk] = g_h1seq[(long long)(tt + 1) * (B_ * MEM_) + b * MEM_ + k0 + kk];
            Ws[rr][kk] = Wout[(k0 + rr) * V_ + ctile * 32 + kk];
        }
        __syncthreads();
        #pragma unroll
        for (int kk = 0; kk < 32; ++kk) {
            float a = As[r][kk];
            float4 w = *reinterpret_cast<const float4*>(&Ws[kk][c4 * 4]);
            acc[0] += a * w.x; acc[1] += a * w.y; acc[2] += a * w.z; acc[3] += a * w.w;
        }
        __syncthreads();
    }
    int rglob = rtile * 32 + r;
    int colbase = ctile * 32 + c4 * 4;
    #pragma unroll
    for (int j = 0; j < 4; ++j)
        out[(long long)rglob * V_ + colbase + j] = acc[j] + bout[colbase + j];
}

// ---------------- launcher: 2 graph nodes total -------------------------------
extern "C" void kernel_launch(void* const* d_in, const int* in_sizes, int n_in,
                              void* d_out, int out_size) {
    const float* x      = (const float*)d_in[0];
    const float* state0 = (const float*)d_in[1];
    const float* state1 = (const float*)d_in[2];
    const float* W0     = (const float*)d_in[3];
    const float* b0     = (const float*)d_in[4];
    const float* W1     = (const float*)d_in[5];
    const float* b1     = (const float*)d_in[6];
    const float* Wout   = (const float*)d_in[7];
    const float* bout   = (const float*)d_in[8];
    float* out = (float*)d_out;

    lstm_persistent<<<NB, NT>>>(x, state0, state1, W0, b0, W1, b1,
                                out + (long long)B_ * T_ * V_);
    proj_kernel<<<dim3(1024, 8), 256>>>(Wout, bout, out);
}